// round 4
// baseline (speedup 1.0000x reference)
#include <cuda_runtime.h>
#include <math.h>

#define NN    8192
#define NL    16
#define NE    (NN * 128)         /* 1048576 edges per layer */
#define EV    (NE / 4)           /* 262144 int4 edge-vectors = 512*512 */
#define NOUT  16
#define EOUT  (NN * NOUT)        /* 131072 output edges */

// Triple-buffered node accumulators + output logit accumulator (scratch; no allocs allowed)
__device__ float g_buf[3][NN];
__device__ float g_oacc[NOUT];

__device__ __forceinline__ float lrelu(float v) { return v >= 0.f ? v : 0.01f * v; }

// Zero g_buf[1] (target of layer 0) and the output accumulator.
__global__ void init_kernel() {
    int i = blockIdx.x * blockDim.x + threadIdx.x;
    if (i < NN) g_buf[1][i] = 0.f;
    if (i < NOUT) g_oacc[i] = 0.f;
}

// One hidden layer. Grid = 512 CTAs x 512 threads: exactly one int4 edge-vector
// per thread (EV = 512*512). Edge loads are issued BEFORE the staging barrier so
// their DRAM latency overlaps the node-table staging. 3 CTAs/SM for latency hiding.
__global__ void __launch_bounds__(512, 3) layer_kernel(
    const int4*   __restrict__ src,
    const int4*   __restrict__ dst,
    const float4* __restrict__ w,
    const float*  __restrict__ vin,
    float*        __restrict__ vout,
    float*        __restrict__ vzero,
    int apply_act)
{
    __shared__ float s_vals[NN];
    const int tid = threadIdx.x;
    const int g   = blockIdx.x * 512 + tid;

    // --- Prefetch this thread's 4 edges (streaming; no reuse) ---
    int4   es = __ldcs(&src[g]);
    int4   ed = __ldcs(&dst[g]);
    float4 ew = __ldcs(&w[g]);

    // --- Stage activated node values into smem (4 float4 per thread) ---
    const float4* vin4 = (const float4*)vin;
    float4* s4 = (float4*)s_vals;
    #pragma unroll
    for (int k = 0; k < 4; ++k) {
        int i = tid + k * 512;
        float4 v = vin4[i];
        if (apply_act) {
            v.x = lrelu(v.x); v.y = lrelu(v.y); v.z = lrelu(v.z); v.w = lrelu(v.w);
        }
        s4[i] = v;
    }

    // --- Fused zeroing of the buffer layer l+1 will scatter into ---
    if (g < NN / 4) ((float4*)vzero)[g] = make_float4(0.f, 0.f, 0.f, 0.f);

    __syncthreads();

    // --- Gather + scatter-add (operands all resident) ---
    atomicAdd(&vout[ed.x], s_vals[es.x] * ew.x);
    atomicAdd(&vout[ed.y], s_vals[es.y] * ew.y);
    atomicAdd(&vout[ed.z], s_vals[es.z] * ew.z);
    atomicAdd(&vout[ed.w], s_vals[es.w] * ew.w);
}

// Output layer: 131072 edges into 16 logits. Per-CTA smem bins, one global
// atomic merge per bin per CTA.
__global__ void __launch_bounds__(256) out_kernel(
    const int*   __restrict__ osrc,
    const int*   __restrict__ odst,
    const float* __restrict__ ow,
    const float* __restrict__ vin)
{
    __shared__ float s_acc[NOUT];
    if (threadIdx.x < NOUT) s_acc[threadIdx.x] = 0.f;
    __syncthreads();

    const int g  = blockIdx.x * blockDim.x + threadIdx.x;
    const int gs = gridDim.x * blockDim.x;
    for (int i = g; i < EOUT; i += gs) {
        float v = lrelu(vin[osrc[i]]);      // vin table is L2/L1-hot (32 KB)
        atomicAdd(&s_acc[odst[i]], v * ow[i]);
    }
    __syncthreads();
    if (threadIdx.x < NOUT) atomicAdd(&g_oacc[threadIdx.x], s_acc[threadIdx.x]);
}

// lrelu + softmax over the 16 logits; one warp.
__global__ void softmax_kernel(float* __restrict__ out) {
    const int t = threadIdx.x;                  // 32 threads
    float v = (t < NOUT) ? lrelu(g_oacc[t]) : -INFINITY;
    float m = v;
    #pragma unroll
    for (int o = 8; o > 0; o >>= 1) m = fmaxf(m, __shfl_xor_sync(0xffffffffu, m, o));
    float e = (t < NOUT) ? __expf(v - m) : 0.f;
    float s = e;
    #pragma unroll
    for (int o = 8; o > 0; o >>= 1) s += __shfl_xor_sync(0xffffffffu, s, o);
    if (t < NOUT) out[t] = e / s;
}

extern "C" void kernel_launch(void* const* d_in, const int* in_sizes, int n_in,
                              void* d_out, int out_size)
{
    // metadata order: x, edge_w, out_w, edge_src, edge_dst, out_src, out_dst
    const float* x        = (const float*)d_in[0];
    const float* edge_w   = (const float*)d_in[1];
    const float* out_w    = (const float*)d_in[2];
    const int*   edge_src = (const int*)  d_in[3];
    const int*   edge_dst = (const int*)  d_in[4];
    const int*   out_src  = (const int*)  d_in[5];
    const int*   out_dst  = (const int*)  d_in[6];
    float* out = (float*)d_out;

    float* buf = nullptr;
    cudaGetSymbolAddress((void**)&buf, g_buf);   // not a stream op; capture-safe

    init_kernel<<<(NN + 255) / 256, 256>>>();

    for (int l = 0; l < NL; ++l) {
        const float* vin  = (l == 0) ? x : (buf + (size_t)(l % 3) * NN);
        float*       vout = buf + (size_t)((l + 1) % 3) * NN;
        float*       vz   = buf + (size_t)((l + 2) % 3) * NN;
        const size_t off  = (size_t)l * NE;
        layer_kernel<<<512, 512>>>(
            (const int4*)(edge_src + off),
            (const int4*)(edge_dst + off),
            (const float4*)(edge_w + off),
            vin, vout, vz, (l > 0) ? 1 : 0);
    }

    // Final hidden values live (raw, pre-activation) in g_buf[NL % 3] == g_buf[1]
    out_kernel<<<152, 256>>>(out_src, out_dst, out_w, buf + (size_t)(NL % 3) * NN);
    softmax_kernel<<<1, 32>>>(out);
}

// round 5
// speedup vs baseline: 2.0375x; 2.0375x over previous
#include <cuda_runtime.h>
#include <math.h>

#define NN    8192
#define NL    16
#define NE    (NN * 128)         /* 1048576 edges per layer */
#define EV    (NE / 4)           /* 262144 int4 edge-vectors */
#define NR    16                 /* accumulator replicas (L2 decontention) */
#define NOUT  16
#define EOUT  (NN * NOUT)        /* 131072 output edges */

// Replicated scatter accumulators (512 KB -> spreads over all LTS partitions),
// reduced node values, output logit accumulator. Scratch via __device__ (no allocs).
__device__ float g_acc[NR][NN];
__device__ float g_val[NN];
__device__ float g_oacc[NOUT];

__device__ __forceinline__ float lrelu(float v) { return v >= 0.f ? v : 0.01f * v; }

// Zero all replicas + logit accumulator (idempotent; needed for first replay's poison).
__global__ void init_kernel() {
    int i = blockIdx.x * blockDim.x + threadIdx.x;      // 128*256 = 32768 float4
    ((float4*)g_acc)[i] = make_float4(0.f, 0.f, 0.f, 0.f);
    if (i < NOUT) g_oacc[i] = 0.f;
}

// One hidden layer: stage vin (already activated) into smem, then scatter-add
// 1M edges into 16 replicated accumulators — warp w of every CTA owns replica w,
// so atomic traffic spreads over the full 512 KB address window (all LTS slices)
// and per-address contention drops 16x.
// Grid: 256 CTAs x 512 threads, 2 int4 edge-vectors per thread.
__global__ void __launch_bounds__(512, 3) layer_kernel(
    const int4*   __restrict__ src,
    const int4*   __restrict__ dst,
    const float4* __restrict__ w,
    const float*  __restrict__ vin)
{
    __shared__ float s_vals[NN];
    const int tid  = threadIdx.x;
    const int base = blockIdx.x * 1024 + tid;

    // Prefetch this thread's 8 edges (streaming) before the staging barrier.
    int4   es0 = __ldcs(&src[base]);       int4   es1 = __ldcs(&src[base + 512]);
    int4   ed0 = __ldcs(&dst[base]);       int4   ed1 = __ldcs(&dst[base + 512]);
    float4 ew0 = __ldcs(&w  [base]);       float4 ew1 = __ldcs(&w  [base + 512]);

    // Stage node values (already activated by reduce_kernel / raw x for layer 0).
    const float4* vin4 = (const float4*)vin;
    float4* s4 = (float4*)s_vals;
    #pragma unroll
    for (int k = 0; k < 4; ++k) {
        int i = tid + k * 512;
        s4[i] = vin4[i];
    }
    __syncthreads();

    // Warp -> replica mapping (16 warps per CTA, NR = 16).
    float* __restrict__ out = &g_acc[tid >> 5][0];

    atomicAdd(&out[ed0.x], s_vals[es0.x] * ew0.x);
    atomicAdd(&out[ed0.y], s_vals[es0.y] * ew0.y);
    atomicAdd(&out[ed0.z], s_vals[es0.z] * ew0.z);
    atomicAdd(&out[ed0.w], s_vals[es0.w] * ew0.w);
    atomicAdd(&out[ed1.x], s_vals[es1.x] * ew1.x);
    atomicAdd(&out[ed1.y], s_vals[es1.y] * ew1.y);
    atomicAdd(&out[ed1.z], s_vals[es1.z] * ew1.z);
    atomicAdd(&out[ed1.w], s_vals[es1.w] * ew1.w);
}

// Fold the 16 replicas into g_val (with activation) and re-zero them for the
// next layer. 32 CTAs x 256 threads = 8192, one node per thread; all accesses
// coalesced, ~1 MB of L2-resident traffic.
__global__ void __launch_bounds__(256) reduce_kernel() {
    const int i = blockIdx.x * blockDim.x + threadIdx.x;
    float s = 0.f;
    #pragma unroll
    for (int r = 0; r < NR; ++r) {
        s += g_acc[r][i];
        g_acc[r][i] = 0.f;
    }
    g_val[i] = lrelu(s);
}

// Output layer: 131072 edges into 16 logits. Per-CTA smem bins, one global
// atomic merge per bin per CTA. g_val is already activated.
__global__ void __launch_bounds__(256) out_kernel(
    const int*   __restrict__ osrc,
    const int*   __restrict__ odst,
    const float* __restrict__ ow)
{
    __shared__ float s_acc[NOUT];
    if (threadIdx.x < NOUT) s_acc[threadIdx.x] = 0.f;
    __syncthreads();

    const int g  = blockIdx.x * blockDim.x + threadIdx.x;
    const int gs = gridDim.x * blockDim.x;
    for (int i = g; i < EOUT; i += gs) {
        atomicAdd(&s_acc[odst[i]], g_val[osrc[i]] * ow[i]);
    }
    __syncthreads();
    if (threadIdx.x < NOUT) atomicAdd(&g_oacc[threadIdx.x], s_acc[threadIdx.x]);
}

// lrelu + softmax over the 16 logits; one warp.
__global__ void softmax_kernel(float* __restrict__ out) {
    const int t = threadIdx.x;                  // 32 threads
    float v = (t < NOUT) ? lrelu(g_oacc[t]) : -INFINITY;
    float m = v;
    #pragma unroll
    for (int o = 8; o > 0; o >>= 1) m = fmaxf(m, __shfl_xor_sync(0xffffffffu, m, o));
    float e = (t < NOUT) ? __expf(v - m) : 0.f;
    float s = e;
    #pragma unroll
    for (int o = 8; o > 0; o >>= 1) s += __shfl_xor_sync(0xffffffffu, s, o);
    if (t < NOUT) out[t] = e / s;
}

extern "C" void kernel_launch(void* const* d_in, const int* in_sizes, int n_in,
                              void* d_out, int out_size)
{
    // metadata order: x, edge_w, out_w, edge_src, edge_dst, out_src, out_dst
    const float* x        = (const float*)d_in[0];
    const float* edge_w   = (const float*)d_in[1];
    const float* out_w    = (const float*)d_in[2];
    const int*   edge_src = (const int*)  d_in[3];
    const int*   edge_dst = (const int*)  d_in[4];
    const int*   out_src  = (const int*)  d_in[5];
    const int*   out_dst  = (const int*)  d_in[6];
    float* out = (float*)d_out;

    float* val = nullptr;
    cudaGetSymbolAddress((void**)&val, g_val);   // not a stream op; capture-safe

    init_kernel<<<128, 256>>>();

    for (int l = 0; l < NL; ++l) {
        const float* vin = (l == 0) ? x : val;
        const size_t off = (size_t)l * NE;
        layer_kernel<<<256, 512>>>(
            (const int4*)(edge_src + off),
            (const int4*)(edge_dst + off),
            (const float4*)(edge_w + off),
            vin);
        reduce_kernel<<<32, 256>>>();
    }

    out_kernel<<<152, 256>>>(out_src, out_dst, out_w);
    softmax_kernel<<<1, 32>>>(out);
}